// round 2
// baseline (speedup 1.0000x reference)
#include <cuda_runtime.h>
#include <math.h>

#define B_   4
#define S_   2048
#define D_   1024
#define MTOT (B_ * S_)

// Scratch (allocation-free rule: __device__ globals)
__device__ float g_Q[MTOT * D_];            // 32 MB
__device__ float g_K[MTOT * D_];            // 32 MB
__device__ float g_V[MTOT * D_];            // 32 MB
__device__ float g_P[(size_t)B_ * S_ * S_]; // 64 MB (scores -> probs in place)

#define BM 128
#define BN 128
#define BK 16
#define PAD 132   // 132*4 = 528 B/row, 16B-aligned

// Shared-tile compute: 16 k-steps of 8x8 outer product per thread.
__device__ __forceinline__ void tile_fma(const float (*As)[PAD], const float (*Bs)[PAD],
                                         int tr, int tc, float acc[8][8])
{
    #pragma unroll
    for (int k = 0; k < BK; k++) {
        float a[8], b[8];
        #pragma unroll
        for (int i = 0; i < 8; i++) a[i] = As[k][tr * 8 + i];
        #pragma unroll
        for (int j = 0; j < 8; j++) b[j] = Bs[k][tc * 8 + j];
        #pragma unroll
        for (int i = 0; i < 8; i++)
            #pragma unroll
            for (int j = 0; j < 8; j++) acc[i][j] = fmaf(a[i], b[j], acc[i][j]);
    }
}

// ---------------------------------------------------------------------------
// QKV: C[z] = X[8192,1024] @ W[z][1024,1024]. NN gemm, register-prefetch pipe.
// ---------------------------------------------------------------------------
__global__ __launch_bounds__(256, 2)
void qkv_kernel(const float* __restrict__ X,
                const float* __restrict__ Wq,
                const float* __restrict__ Wk,
                const float* __restrict__ Wv)
{
    const float* W = (blockIdx.z == 0) ? Wq : ((blockIdx.z == 1) ? Wk : Wv);
    float*       C = (blockIdx.z == 0) ? g_Q : ((blockIdx.z == 1) ? g_K : g_V);
    const int m0 = blockIdx.y * BM;
    const int n0 = blockIdx.x * BN;

    __shared__ float As[BK][PAD];
    __shared__ float Bs[BK][PAD];

    const int tid = threadIdx.x;
    const int tr = tid >> 4;
    const int tc = tid & 15;

    // A-stage addressing (transposed store): idx = tid + 256*i
    const int arow0 = tid >> 2,        ac4 = tid & 3;          // i=0
    const int arow1 = (tid + 256) >> 2;                        // i=1, same c4
    // B-stage addressing (direct store)
    const int brow0 = tid >> 5,        bc4 = tid & 31;         // i=0
    const int brow1 = (tid + 256) >> 5;                        // i=1

    float acc[8][8];
    #pragma unroll
    for (int i = 0; i < 8; i++)
        #pragma unroll
        for (int j = 0; j < 8; j++) acc[i][j] = 0.0f;

    float4 ra0, ra1, rb0, rb1;
    // prefetch k0 = 0
    ra0 = *reinterpret_cast<const float4*>(&X[(size_t)(m0 + arow0) * D_ + ac4 * 4]);
    ra1 = *reinterpret_cast<const float4*>(&X[(size_t)(m0 + arow1) * D_ + ac4 * 4]);
    rb0 = *reinterpret_cast<const float4*>(&W[(size_t)brow0 * D_ + n0 + bc4 * 4]);
    rb1 = *reinterpret_cast<const float4*>(&W[(size_t)brow1 * D_ + n0 + bc4 * 4]);

    for (int k0 = 0; k0 < D_; k0 += BK) {
        As[ac4 * 4 + 0][arow0] = ra0.x; As[ac4 * 4 + 1][arow0] = ra0.y;
        As[ac4 * 4 + 2][arow0] = ra0.z; As[ac4 * 4 + 3][arow0] = ra0.w;
        As[ac4 * 4 + 0][arow1] = ra1.x; As[ac4 * 4 + 1][arow1] = ra1.y;
        As[ac4 * 4 + 2][arow1] = ra1.z; As[ac4 * 4 + 3][arow1] = ra1.w;
        *reinterpret_cast<float4*>(&Bs[brow0][bc4 * 4]) = rb0;
        *reinterpret_cast<float4*>(&Bs[brow1][bc4 * 4]) = rb1;
        __syncthreads();

        const int kn = k0 + BK;
        if (kn < D_) {  // issue next tile's loads; latency hides under compute
            ra0 = *reinterpret_cast<const float4*>(&X[(size_t)(m0 + arow0) * D_ + kn + ac4 * 4]);
            ra1 = *reinterpret_cast<const float4*>(&X[(size_t)(m0 + arow1) * D_ + kn + ac4 * 4]);
            rb0 = *reinterpret_cast<const float4*>(&W[(size_t)(kn + brow0) * D_ + n0 + bc4 * 4]);
            rb1 = *reinterpret_cast<const float4*>(&W[(size_t)(kn + brow1) * D_ + n0 + bc4 * 4]);
        }

        tile_fma(As, Bs, tr, tc, acc);
        __syncthreads();
    }

    #pragma unroll
    for (int i = 0; i < 8; i++) {
        int m = m0 + tr * 8 + i;
        #pragma unroll
        for (int j = 0; j < 8; j += 4) {
            float4 v = make_float4(acc[i][j], acc[i][j+1], acc[i][j+2], acc[i][j+3]);
            *reinterpret_cast<float4*>(&C[(size_t)m * D_ + n0 + tc * 8 + j]) = v;
        }
    }
}

// ---------------------------------------------------------------------------
// Scores: P_b = (Q_b @ K_b^T) / sqrt(D). NT gemm, causal block skip, pipelined.
// ---------------------------------------------------------------------------
__global__ __launch_bounds__(256, 2)
void scores_kernel()
{
    const int bx = blockIdx.x;   // k block
    const int by = blockIdx.y;   // q block
    if (bx > by) return;         // strictly above causal diagonal
    const int b = blockIdx.z;

    const float* Q  = g_Q + (size_t)b * S_ * D_;
    const float* Km = g_K + (size_t)b * S_ * D_;
    float*       C  = g_P + (size_t)b * S_ * S_;
    const int m0 = by * BM;
    const int n0 = bx * BN;

    __shared__ float As[BK][PAD];
    __shared__ float Bs[BK][PAD];

    const int tid = threadIdx.x;
    const int tr = tid >> 4;
    const int tc = tid & 15;

    const int arow0 = tid >> 2, ac4 = tid & 3;
    const int arow1 = (tid + 256) >> 2;

    float acc[8][8];
    #pragma unroll
    for (int i = 0; i < 8; i++)
        #pragma unroll
        for (int j = 0; j < 8; j++) acc[i][j] = 0.0f;

    float4 ra0, ra1, rb0, rb1;
    ra0 = *reinterpret_cast<const float4*>(&Q [(size_t)(m0 + arow0) * D_ + ac4 * 4]);
    ra1 = *reinterpret_cast<const float4*>(&Q [(size_t)(m0 + arow1) * D_ + ac4 * 4]);
    rb0 = *reinterpret_cast<const float4*>(&Km[(size_t)(n0 + arow0) * D_ + ac4 * 4]);
    rb1 = *reinterpret_cast<const float4*>(&Km[(size_t)(n0 + arow1) * D_ + ac4 * 4]);

    for (int k0 = 0; k0 < D_; k0 += BK) {
        As[ac4 * 4 + 0][arow0] = ra0.x; As[ac4 * 4 + 1][arow0] = ra0.y;
        As[ac4 * 4 + 2][arow0] = ra0.z; As[ac4 * 4 + 3][arow0] = ra0.w;
        As[ac4 * 4 + 0][arow1] = ra1.x; As[ac4 * 4 + 1][arow1] = ra1.y;
        As[ac4 * 4 + 2][arow1] = ra1.z; As[ac4 * 4 + 3][arow1] = ra1.w;
        Bs[ac4 * 4 + 0][arow0] = rb0.x; Bs[ac4 * 4 + 1][arow0] = rb0.y;
        Bs[ac4 * 4 + 2][arow0] = rb0.z; Bs[ac4 * 4 + 3][arow0] = rb0.w;
        Bs[ac4 * 4 + 0][arow1] = rb1.x; Bs[ac4 * 4 + 1][arow1] = rb1.y;
        Bs[ac4 * 4 + 2][arow1] = rb1.z; Bs[ac4 * 4 + 3][arow1] = rb1.w;
        __syncthreads();

        const int kn = k0 + BK;
        if (kn < D_) {
            ra0 = *reinterpret_cast<const float4*>(&Q [(size_t)(m0 + arow0) * D_ + kn + ac4 * 4]);
            ra1 = *reinterpret_cast<const float4*>(&Q [(size_t)(m0 + arow1) * D_ + kn + ac4 * 4]);
            rb0 = *reinterpret_cast<const float4*>(&Km[(size_t)(n0 + arow0) * D_ + kn + ac4 * 4]);
            rb1 = *reinterpret_cast<const float4*>(&Km[(size_t)(n0 + arow1) * D_ + kn + ac4 * 4]);
        }

        tile_fma(As, Bs, tr, tc, acc);
        __syncthreads();
    }

    const float scale = 0.03125f;  // 1/sqrt(1024)
    #pragma unroll
    for (int i = 0; i < 8; i++) {
        int m = m0 + tr * 8 + i;
        #pragma unroll
        for (int j = 0; j < 8; j += 4) {
            float4 v = make_float4(acc[i][j] * scale, acc[i][j+1] * scale,
                                   acc[i][j+2] * scale, acc[i][j+3] * scale);
            *reinterpret_cast<float4*>(&C[(size_t)m * S_ + n0 + tc * 8 + j]) = v;
        }
    }
}

// ---------------------------------------------------------------------------
// Softmax: per row i use only j <= i; write probs, zero the rest of the row.
// ---------------------------------------------------------------------------
__global__ void softmax_kernel()
{
    const int r = blockIdx.x;          // 0 .. MTOT-1
    const int b = r / S_, i = r % S_;
    float* row = g_P + (size_t)b * S_ * S_ + (size_t)i * S_;
    const int len = i + 1;
    const int tid = threadIdx.x;

    __shared__ float red[256];

    float mx = -INFINITY;
    for (int j = tid; j < len; j += 256) mx = fmaxf(mx, row[j]);
    red[tid] = mx; __syncthreads();
    for (int s = 128; s > 0; s >>= 1) {
        if (tid < s) red[tid] = fmaxf(red[tid], red[tid + s]);
        __syncthreads();
    }
    mx = red[0];
    __syncthreads();

    float sum = 0.0f;
    for (int j = tid; j < len; j += 256) sum += __expf(row[j] - mx);
    red[tid] = sum; __syncthreads();
    for (int s = 128; s > 0; s >>= 1) {
        if (tid < s) red[tid] += red[tid + s];
        __syncthreads();
    }
    const float inv = 1.0f / red[0];
    __syncthreads();

    for (int j = tid; j < len; j += 256) row[j] = __expf(row[j] - mx) * inv;
    for (int j = len + tid; j < S_; j += 256) row[j] = 0.0f;
}

// ---------------------------------------------------------------------------
// PV: Out_b = P_b @ V_b. NN gemm; k only runs to m0+BM (rest of P row is 0).
// ---------------------------------------------------------------------------
__global__ __launch_bounds__(256, 2)
void pv_kernel(float* __restrict__ Out)
{
    const int b  = blockIdx.z;
    const int m0 = blockIdx.y * BM;
    const int n0 = blockIdx.x * BN;
    const float* P = g_P + (size_t)b * S_ * S_;
    const float* V = g_V + (size_t)b * S_ * D_;
    float*       C = Out + (size_t)b * S_ * D_;
    const int kend = m0 + BM;   // <= S_

    __shared__ float As[BK][PAD];
    __shared__ float Bs[BK][PAD];

    const int tid = threadIdx.x;
    const int tr = tid >> 4;
    const int tc = tid & 15;

    const int arow0 = tid >> 2, ac4 = tid & 3;
    const int arow1 = (tid + 256) >> 2;
    const int brow0 = tid >> 5, bc4 = tid & 31;
    const int brow1 = (tid + 256) >> 5;

    float acc[8][8];
    #pragma unroll
    for (int i = 0; i < 8; i++)
        #pragma unroll
        for (int j = 0; j < 8; j++) acc[i][j] = 0.0f;

    float4 ra0, ra1, rb0, rb1;
    ra0 = *reinterpret_cast<const float4*>(&P[(size_t)(m0 + arow0) * S_ + ac4 * 4]);
    ra1 = *reinterpret_cast<const float4*>(&P[(size_t)(m0 + arow1) * S_ + ac4 * 4]);
    rb0 = *reinterpret_cast<const float4*>(&V[(size_t)brow0 * D_ + n0 + bc4 * 4]);
    rb1 = *reinterpret_cast<const float4*>(&V[(size_t)brow1 * D_ + n0 + bc4 * 4]);

    for (int k0 = 0; k0 < kend; k0 += BK) {
        As[ac4 * 4 + 0][arow0] = ra0.x; As[ac4 * 4 + 1][arow0] = ra0.y;
        As[ac4 * 4 + 2][arow0] = ra0.z; As[ac4 * 4 + 3][arow0] = ra0.w;
        As[ac4 * 4 + 0][arow1] = ra1.x; As[ac4 * 4 + 1][arow1] = ra1.y;
        As[ac4 * 4 + 2][arow1] = ra1.z; As[ac4 * 4 + 3][arow1] = ra1.w;
        *reinterpret_cast<float4*>(&Bs[brow0][bc4 * 4]) = rb0;
        *reinterpret_cast<float4*>(&Bs[brow1][bc4 * 4]) = rb1;
        __syncthreads();

        const int kn = k0 + BK;
        if (kn < kend) {
            ra0 = *reinterpret_cast<const float4*>(&P[(size_t)(m0 + arow0) * S_ + kn + ac4 * 4]);
            ra1 = *reinterpret_cast<const float4*>(&P[(size_t)(m0 + arow1) * S_ + kn + ac4 * 4]);
            rb0 = *reinterpret_cast<const float4*>(&V[(size_t)(kn + brow0) * D_ + n0 + bc4 * 4]);
            rb1 = *reinterpret_cast<const float4*>(&V[(size_t)(kn + brow1) * D_ + n0 + bc4 * 4]);
        }

        tile_fma(As, Bs, tr, tc, acc);
        __syncthreads();
    }

    #pragma unroll
    for (int i = 0; i < 8; i++) {
        int m = m0 + tr * 8 + i;
        #pragma unroll
        for (int j = 0; j < 8; j += 4) {
            float4 v = make_float4(acc[i][j], acc[i][j+1], acc[i][j+2], acc[i][j+3]);
            *reinterpret_cast<float4*>(&C[(size_t)m * D_ + n0 + tc * 8 + j]) = v;
        }
    }
}

// ---------------------------------------------------------------------------
extern "C" void kernel_launch(void* const* d_in, const int* in_sizes, int n_in,
                              void* d_out, int out_size)
{
    const float* x  = (const float*)d_in[0];
    const float* Wq = (const float*)d_in[1];
    const float* Wk = (const float*)d_in[2];
    const float* Wv = (const float*)d_in[3];
    float* out = (float*)d_out;

    qkv_kernel   <<<dim3(D_ / BN, MTOT / BM, 3), 256>>>(x, Wq, Wk, Wv);
    scores_kernel<<<dim3(S_ / BN, S_ / BM, B_), 256>>>();
    softmax_kernel<<<MTOT, 256>>>();
    pv_kernel    <<<dim3(D_ / BN, S_ / BM, B_), 256>>>(out);
}

// round 12
// speedup vs baseline: 2.3402x; 2.3402x over previous
#include <cuda_runtime.h>
#include <cuda_bf16.h>
#include <stdint.h>
#include <math.h>

#define B_   4
#define S_   2048
#define D_   1024
#define MTOT (B_ * S_)

// Scratch (__device__ globals; allocation-free rule)
__device__ float g_Q [(size_t)MTOT * D_];        // [b*s][d]
__device__ float g_K [(size_t)MTOT * D_];        // [b*s][d]
__device__ float g_Vf[(size_t)MTOT * D_];        // [b][s][d]
__device__ float g_Vt[(size_t)MTOT * D_];        // [b][d][s]
__device__ float g_Wt[(size_t)3 * D_ * D_];      // [z][n][k]
__device__ float g_P [(size_t)B_ * S_ * S_];     // [b][sq][sk]

// ---------------- MMA GEMM configuration ----------------
#define KC    64                 // k per chunk
#define TPAD  72                 // bf16 per smem row (64 + 8 pad) -> 144 B stride
#define TILE_B (128 * TPAD * 2)  // 18432 B per tile
#define O_AHI 0
#define O_ALO (TILE_B)
#define O_BHI (2 * TILE_B)
#define O_BLO (3 * TILE_B)
#define BUF_B (4 * TILE_B)       // 73728 B per buffer
#define SMEM_TOTAL (2 * BUF_B)   // 147456 B (double buffered)

static __device__ __forceinline__ uint32_t bf2u(__nv_bfloat162 h) {
    return *reinterpret_cast<uint32_t*>(&h);
}
static __device__ __forceinline__ uint32_t lds32(const char* p) {
    return *reinterpret_cast<const uint32_t*>(p);
}

// mma.sync m16n8k16 bf16 (baseline PTX, no arch-feature target needed)
static __device__ __forceinline__ void mma_bf16(float c[4],
    uint32_t a0, uint32_t a1, uint32_t a2, uint32_t a3, uint32_t b0, uint32_t b1)
{
    asm volatile(
        "mma.sync.aligned.m16n8k16.row.col.f32.bf16.bf16.f32 "
        "{%0,%1,%2,%3}, {%4,%5,%6,%7}, {%8,%9}, {%0,%1,%2,%3};"
        : "+f"(c[0]), "+f"(c[1]), "+f"(c[2]), "+f"(c[3])
        : "r"(a0), "r"(a1), "r"(a2), "r"(a3), "r"(b0), "r"(b1));
}

// 8 fp32 -> split hi/lo bf16, swizzle-free padded STS (16B per thread)
static __device__ __forceinline__ void cvt_sts8(char* hi, char* lo,
                                                float4 u, float4 v, int row, int lane8)
{
    __nv_bfloat162 h0 = __floats2bfloat162_rn(u.x, u.y);
    __nv_bfloat162 h1 = __floats2bfloat162_rn(u.z, u.w);
    __nv_bfloat162 h2 = __floats2bfloat162_rn(v.x, v.y);
    __nv_bfloat162 h3 = __floats2bfloat162_rn(v.z, v.w);
    __nv_bfloat162 l0 = __floats2bfloat162_rn(u.x - __bfloat162float(h0.x),
                                              u.y - __bfloat162float(h0.y));
    __nv_bfloat162 l1 = __floats2bfloat162_rn(u.z - __bfloat162float(h1.x),
                                              u.w - __bfloat162float(h1.y));
    __nv_bfloat162 l2 = __floats2bfloat162_rn(v.x - __bfloat162float(h2.x),
                                              v.y - __bfloat162float(h2.y));
    __nv_bfloat162 l3 = __floats2bfloat162_rn(v.z - __bfloat162float(h3.x),
                                              v.w - __bfloat162float(h3.y));
    const int off = row * (TPAD * 2) + lane8 * 16;
    *reinterpret_cast<uint4*>(hi + off) = make_uint4(bf2u(h0), bf2u(h1), bf2u(h2), bf2u(h3));
    *reinterpret_cast<uint4*>(lo + off) = make_uint4(bf2u(l0), bf2u(l1), bf2u(l2), bf2u(l3));
}

// ---------------- core GEMM: C(128x128) = A(128xK) @ B(128xK)^T, split-bf16 ----------------
// A rows: m (lda), B rows: n (ldb); both K-contiguous fp32. C pre-offset, stride ldc.
static __device__ __forceinline__ void gemm_mma(
    const float* __restrict__ A, size_t lda,
    const float* __restrict__ Bm, size_t ldb,
    int nchunks, float scale, float* __restrict__ C, size_t ldc)
{
    extern __shared__ char smem[];
    const int tid = threadIdx.x;
    const int lane8 = tid & 7;       // col-group (8 fp32)
    const int lrow  = tid >> 3;      // 0..63
    const int wid = tid >> 5, lane = tid & 31;
    const int g = lane >> 2, tg = lane & 3;
    const int wm = wid & 3, wn = wid >> 2;     // 4x4 warp grid, warp tile 32x32

    float acc[2][4][4];
    #pragma unroll
    for (int mt = 0; mt < 2; mt++)
        #pragma unroll
        for (int nt = 0; nt < 4; nt++)
            #pragma unroll
            for (int q = 0; q < 4; q++) acc[mt][nt][q] = 0.0f;

    // prologue: chunk 0 -> buf 0
    {
        char* buf = smem;
        const float* Ar = A + (size_t)lrow * lda + lane8 * 8;
        const float* Br = Bm + (size_t)lrow * ldb + lane8 * 8;
        float4 a0 = *reinterpret_cast<const float4*>(Ar);
        float4 a1 = *reinterpret_cast<const float4*>(Ar + 4);
        float4 a2 = *reinterpret_cast<const float4*>(Ar + 64 * lda);
        float4 a3 = *reinterpret_cast<const float4*>(Ar + 64 * lda + 4);
        float4 b0 = *reinterpret_cast<const float4*>(Br);
        float4 b1 = *reinterpret_cast<const float4*>(Br + 4);
        float4 b2 = *reinterpret_cast<const float4*>(Br + 64 * ldb);
        float4 b3 = *reinterpret_cast<const float4*>(Br + 64 * ldb + 4);
        cvt_sts8(buf + O_AHI, buf + O_ALO, a0, a1, lrow, lane8);
        cvt_sts8(buf + O_AHI, buf + O_ALO, a2, a3, lrow + 64, lane8);
        cvt_sts8(buf + O_BHI, buf + O_BLO, b0, b1, lrow, lane8);
        cvt_sts8(buf + O_BHI, buf + O_BLO, b2, b3, lrow + 64, lane8);
    }
    __syncthreads();

    for (int c = 0; c < nchunks; c++) {
        char* cur = smem + (c & 1) * BUF_B;
        char* nxt = smem + ((c + 1) & 1) * BUF_B;
        const bool pf = (c + 1 < nchunks);

        float4 pa0, pa1, pa2, pa3, pb0, pb1, pb2, pb3;
        const float* An = A  + (size_t)(c + 1) * KC;
        const float* Bn = Bm + (size_t)(c + 1) * KC;
        if (pf) {   // stage 1: A global loads (latency hidden under ksteps 0-1)
            const float* Ar = An + (size_t)lrow * lda + lane8 * 8;
            pa0 = *reinterpret_cast<const float4*>(Ar);
            pa1 = *reinterpret_cast<const float4*>(Ar + 4);
            pa2 = *reinterpret_cast<const float4*>(Ar + 64 * lda);
            pa3 = *reinterpret_cast<const float4*>(Ar + 64 * lda + 4);
        }

        #pragma unroll
        for (int ks = 0; ks < 4; ks++) {
            if (ks == 2 && pf) {   // A regs -> next buf; stage 2: B global loads
                cvt_sts8(nxt + O_AHI, nxt + O_ALO, pa0, pa1, lrow, lane8);
                cvt_sts8(nxt + O_AHI, nxt + O_ALO, pa2, pa3, lrow + 64, lane8);
                const float* Br = Bn + (size_t)lrow * ldb + lane8 * 8;
                pb0 = *reinterpret_cast<const float4*>(Br);
                pb1 = *reinterpret_cast<const float4*>(Br + 4);
                pb2 = *reinterpret_cast<const float4*>(Br + 64 * ldb);
                pb3 = *reinterpret_cast<const float4*>(Br + 64 * ldb + 4);
            }
            const int k0 = ks * 16;
            uint32_t ah[2][4], al[2][4], bh[4][2], bl[4][2];
            #pragma unroll
            for (int mt = 0; mt < 2; mt++) {
                const int r1 = (wm * 32 + mt * 16 + g) * (TPAD * 2);
                const int r2 = r1 + 8 * (TPAD * 2);
                const int c1 = (k0 + tg * 2) * 2, c2 = (k0 + 8 + tg * 2) * 2;
                ah[mt][0] = lds32(cur + O_AHI + r1 + c1);
                ah[mt][1] = lds32(cur + O_AHI + r2 + c1);
                ah[mt][2] = lds32(cur + O_AHI + r1 + c2);
                ah[mt][3] = lds32(cur + O_AHI + r2 + c2);
                al[mt][0] = lds32(cur + O_ALO + r1 + c1);
                al[mt][1] = lds32(cur + O_ALO + r2 + c1);
                al[mt][2] = lds32(cur + O_ALO + r1 + c2);
                al[mt][3] = lds32(cur + O_ALO + r2 + c2);
            }
            #pragma unroll
            for (int nt = 0; nt < 4; nt++) {
                const int rn = (wn * 32 + nt * 8 + g) * (TPAD * 2);
                const int c1 = (k0 + tg * 2) * 2, c2 = (k0 + 8 + tg * 2) * 2;
                bh[nt][0] = lds32(cur + O_BHI + rn + c1);
                bh[nt][1] = lds32(cur + O_BHI + rn + c2);
                bl[nt][0] = lds32(cur + O_BLO + rn + c1);
                bl[nt][1] = lds32(cur + O_BLO + rn + c2);
            }
            #pragma unroll
            for (int mt = 0; mt < 2; mt++)
                #pragma unroll
                for (int nt = 0; nt < 4; nt++) {
                    mma_bf16(acc[mt][nt], ah[mt][0], ah[mt][1], ah[mt][2], ah[mt][3],
                             bh[nt][0], bh[nt][1]);
                    mma_bf16(acc[mt][nt], ah[mt][0], ah[mt][1], ah[mt][2], ah[mt][3],
                             bl[nt][0], bl[nt][1]);
                    mma_bf16(acc[mt][nt], al[mt][0], al[mt][1], al[mt][2], al[mt][3],
                             bh[nt][0], bh[nt][1]);
                }
        }
        if (pf) {   // B regs -> next buf
            cvt_sts8(nxt + O_BHI, nxt + O_BLO, pb0, pb1, lrow, lane8);
            cvt_sts8(nxt + O_BHI, nxt + O_BLO, pb2, pb3, lrow + 64, lane8);
        }
        __syncthreads();
    }

    // epilogue: acc -> C
    #pragma unroll
    for (int mt = 0; mt < 2; mt++) {
        const int r = wm * 32 + mt * 16 + g;
        #pragma unroll
        for (int nt = 0; nt < 4; nt++) {
            const int col = wn * 32 + nt * 8 + tg * 2;
            *reinterpret_cast<float2*>(C + (size_t)r * ldc + col) =
                make_float2(acc[mt][nt][0] * scale, acc[mt][nt][1] * scale);
            *reinterpret_cast<float2*>(C + (size_t)(r + 8) * ldc + col) =
                make_float2(acc[mt][nt][2] * scale, acc[mt][nt][3] * scale);
        }
    }
}

// ---------------- GEMM kernels ----------------
__global__ __launch_bounds__(512, 1)
void qkv_mma_kernel(const float* __restrict__ X)
{
    const int z  = blockIdx.z;
    const int m0 = blockIdx.y * 128;
    const int n0 = blockIdx.x * 128;
    const float* A = X + (size_t)m0 * D_;
    const float* Bm = g_Wt + (size_t)z * D_ * D_ + (size_t)n0 * D_;
    float* C = ((z == 0) ? g_Q : (z == 1) ? g_K : g_Vf) + (size_t)m0 * D_ + n0;
    gemm_mma(A, D_, Bm, D_, D_ / KC, 1.0f, C, D_);
}

__global__ __launch_bounds__(512, 1)
void scores_mma_kernel()
{
    const int bx = blockIdx.x, by = blockIdx.y;
    if (bx > by) return;                         // strictly above causal diagonal
    const int b  = blockIdx.z;
    const int m0 = by * 128, n0 = bx * 128;
    const float* A  = g_Q + (size_t)b * S_ * D_ + (size_t)m0 * D_;
    const float* Bm = g_K + (size_t)b * S_ * D_ + (size_t)n0 * D_;
    float* C = g_P + (size_t)b * S_ * S_ + (size_t)m0 * S_ + n0;
    gemm_mma(A, D_, Bm, D_, D_ / KC, 0.03125f, C, S_);   // 1/sqrt(1024)
}

__global__ __launch_bounds__(512, 1)
void pv_mma_kernel(float* __restrict__ Out)
{
    const int b  = blockIdx.z;
    const int by = blockIdx.y;
    const int m0 = by * 128, n0 = blockIdx.x * 128;
    const float* A  = g_P  + (size_t)b * S_ * S_ + (size_t)m0 * S_;   // zeros to block end
    const float* Bm = g_Vt + (size_t)b * D_ * S_ + (size_t)n0 * S_;
    float* C = Out + ((size_t)b * S_ + m0) * D_ + n0;
    gemm_mma(A, S_, Bm, S_, 2 * by + 2, 1.0f, C, D_);    // kend = m0 + 128
}

// ---------------- transposes (fp32) ----------------
__global__ __launch_bounds__(256)
void transpose_w_kernel(const float* __restrict__ Wq, const float* __restrict__ Wk,
                        const float* __restrict__ Wv)
{
    const int z = blockIdx.z;
    const float* in = (z == 0) ? Wq : (z == 1) ? Wk : Wv;   // [k][n]
    float* out = g_Wt + (size_t)z * D_ * D_;                 // [n][k]
    __shared__ float t[32][33];
    const int tx = threadIdx.x & 31, ty = threadIdx.x >> 5;
    const int bx = blockIdx.x, by = blockIdx.y;
    #pragma unroll
    for (int i = 0; i < 32; i += 8)
        t[ty + i][tx] = in[(size_t)(by * 32 + ty + i) * D_ + bx * 32 + tx];
    __syncthreads();
    #pragma unroll
    for (int i = 0; i < 32; i += 8)
        out[(size_t)(bx * 32 + ty + i) * D_ + by * 32 + tx] = t[tx][ty + i];
}

__global__ __launch_bounds__(256)
void transpose_v_kernel()
{
    const int b = blockIdx.z;
    const float* in = g_Vf + (size_t)b * S_ * D_;  // [s][d]
    float* out = g_Vt + (size_t)b * D_ * S_;       // [d][s]
    __shared__ float t[32][33];
    const int tx = threadIdx.x & 31, ty = threadIdx.x >> 5;
    const int bx = blockIdx.x, by = blockIdx.y;    // bx: d-tile, by: s-tile
    #pragma unroll
    for (int i = 0; i < 32; i += 8)
        t[ty + i][tx] = in[(size_t)(by * 32 + ty + i) * D_ + bx * 32 + tx];
    __syncthreads();
    #pragma unroll
    for (int i = 0; i < 32; i += 8)
        out[(size_t)(bx * 32 + ty + i) * S_ + by * 32 + tx] = t[tx][ty + i];
}

// ---------------- softmax (row-cached, block-trimmed zero fill) ----------------
__global__ __launch_bounds__(256)
void softmax_kernel()
{
    const int r = blockIdx.x;
    const int b = r >> 11;
    const int i = r & 2047;
    float* row = g_P + (size_t)b * S_ * S_ + (size_t)i * S_;
    const int len = i + 1;
    const int tid = threadIdx.x;

    __shared__ float rowbuf[S_];
    __shared__ float red[32];

    float mx = -1e30f;
    for (int j = tid; j < len; j += 256) { float v = row[j]; rowbuf[j] = v; mx = fmaxf(mx, v); }
    #pragma unroll
    for (int o = 16; o; o >>= 1) mx = fmaxf(mx, __shfl_xor_sync(~0u, mx, o));
    if ((tid & 31) == 0) red[tid >> 5] = mx;
    __syncthreads();
    if (tid < 32) {
        float v = (tid < 8) ? red[tid] : -1e30f;
        #pragma unroll
        for (int o = 4; o; o >>= 1) v = fmaxf(v, __shfl_xor_sync(~0u, v, o));
        red[tid] = v;
    }
    __syncthreads();
    mx = red[0];
    __syncthreads();

    float sum = 0.0f;
    for (int j = tid; j < len; j += 256) {
        float e = __expf(rowbuf[j] - mx);
        rowbuf[j] = e;
        sum += e;
    }
    #pragma unroll
    for (int o = 16; o; o >>= 1) sum += __shfl_xor_sync(~0u, sum, o);
    if ((tid & 31) == 0) red[tid >> 5] = sum;
    __syncthreads();
    if (tid < 32) {
        float v = (tid < 8) ? red[tid] : 0.0f;
        #pragma unroll
        for (int o = 4; o; o >>= 1) v += __shfl_xor_sync(~0u, v, o);
        red[tid] = v;
    }
    __syncthreads();
    const float inv = 1.0f / red[0];

    for (int j = tid; j < len; j += 256) row[j] = rowbuf[j] * inv;
    const int zend = ((i >> 7) + 1) << 7;        // zero to end of this 128-row q-block
    for (int j = len + tid; j < zend; j += 256) row[j] = 0.0f;
}

// ---------------- launch ----------------
extern "C" void kernel_launch(void* const* d_in, const int* in_sizes, int n_in,
                              void* d_out, int out_size)
{
    const float* x  = (const float*)d_in[0];
    const float* Wq = (const float*)d_in[1];
    const float* Wk = (const float*)d_in[2];
    const float* Wv = (const float*)d_in[3];
    float* out = (float*)d_out;

    cudaFuncSetAttribute(qkv_mma_kernel,    cudaFuncAttributeMaxDynamicSharedMemorySize, SMEM_TOTAL);
    cudaFuncSetAttribute(scores_mma_kernel, cudaFuncAttributeMaxDynamicSharedMemorySize, SMEM_TOTAL);
    cudaFuncSetAttribute(pv_mma_kernel,     cudaFuncAttributeMaxDynamicSharedMemorySize, SMEM_TOTAL);

    transpose_w_kernel<<<dim3(32, 32, 3), 256>>>(Wq, Wk, Wv);
    qkv_mma_kernel<<<dim3(8, 64, 3), 512, SMEM_TOTAL>>>(x);
    transpose_v_kernel<<<dim3(32, 64, 4), 256>>>();
    scores_mma_kernel<<<dim3(16, 16, 4), 512, SMEM_TOTAL>>>();
    softmax_kernel<<<MTOT, 256>>>();
    pv_mma_kernel<<<dim3(8, 16, 4), 512, SMEM_TOTAL>>>(out);
}